// round 2
// baseline (speedup 1.0000x reference)
#include <cuda_runtime.h>
#include <cstdint>

#define BB 8
#define SS 2048
#define DD 768
#define HH 12

typedef unsigned long long ull;

// scratch (allocation-free rule: __device__ globals)
__device__ float g_q[BB * SS * HH];
__device__ float g_k[BB * SS * HH];
__device__ float g_v[BB * SS * HH];

// ---------- f32x2 helpers (FFMA2 path, PTX-only) ----------
__device__ __forceinline__ ull pk2(float a, float b) {
    ull r;
    asm("mov.b64 %0, {%1, %2};"
        : "=l"(r) : "r"(__float_as_uint(a)), "r"(__float_as_uint(b)));
    return r;
}
__device__ __forceinline__ void upk2(ull v, float& a, float& b) {
    unsigned int x, y;
    asm("mov.b64 {%0, %1}, %2;" : "=r"(x), "=r"(y) : "l"(v));
    a = __uint_as_float(x);
    b = __uint_as_float(y);
}
__device__ __forceinline__ void fma2(ull& d, ull a, ull b) {
    asm("fma.rn.f32x2 %0, %1, %2, %0;" : "+l"(d) : "l"(a), "l"(b));
}
__device__ __forceinline__ ull add2(ull a, ull b) {
    ull r;
    asm("add.rn.f32x2 %0, %1, %2;" : "=l"(r) : "l"(a), "l"(b));
    return r;
}

// =====================================================================
// Kernel 1: fused QKV projection.  y[row][0..35] = x[row][:] @ [Wq|Wk|Wv]
// 64 rows per block, thread-per-row, d chunked by 32 through shared.
// Weight pairs (h, h+1) are contiguous in memory -> load as ulonglong2,
// directly usable as FFMA2 operands. Only x needs a (x,x) pack per d.
// =====================================================================
__global__ __launch_bounds__(64) void proj_kernel(
    const float* __restrict__ x,
    const float* __restrict__ wq,
    const float* __restrict__ wk,
    const float* __restrict__ wv)
{
    __shared__ float xs[64 * 33];          // pad 33: conflict-free column reads
    __shared__ ulonglong2 ws[32 * 9];      // [c][j]: 36 floats per c (q:0-11,k:12-23,v:24-35)

    const int tid = threadIdx.x;
    const long rowBase = (long)blockIdx.x * 64;

    ull acc[18];
#pragma unroll
    for (int i = 0; i < 18; i++) acc[i] = 0ULL;

    for (int dc = 0; dc < DD; dc += 32) {
        __syncthreads();
        // stage x chunk: 64 rows x 32 cols, coalesced (one row per warp-pass)
#pragma unroll
        for (int i = 0; i < 32; i++) {
            int idx = tid + i * 64;
            int r = idx >> 5, c = idx & 31;
            xs[r * 33 + c] = x[(rowBase + r) * DD + dc + c];
        }
        // stage W chunk
        float* wsf = (float*)ws;
        for (int i = tid; i < 32 * 12; i += 64) {
            int c = i / 12;
            int h = i - c * 12;
            int gi = (dc + c) * HH + h;
            wsf[c * 36 + h]      = wq[gi];
            wsf[c * 36 + 12 + h] = wk[gi];
            wsf[c * 36 + 24 + h] = wv[gi];
        }
        __syncthreads();

        const float* myx = &xs[tid * 33];
#pragma unroll
        for (int c = 0; c < 32; c++) {
            float xv = myx[c];
            ull x2 = pk2(xv, xv);
            const ulonglong2* wrow = &ws[c * 9];
#pragma unroll
            for (int j = 0; j < 9; j++) {
                ulonglong2 u = wrow[j];     // (w4j,w4j+1),(w4j+2,w4j+3) pre-packed
                fma2(acc[2 * j],     x2, u.x);
                fma2(acc[2 * j + 1], x2, u.y);
            }
        }
    }

    float o[36];
#pragma unroll
    for (int j = 0; j < 18; j++) upk2(acc[j], o[2 * j], o[2 * j + 1]);

    const long row = rowBase + tid;
    float4* qo = (float4*)&g_q[row * HH];
    float4* ko = (float4*)&g_k[row * HH];
    float4* vo = (float4*)&g_v[row * HH];
    qo[0] = make_float4(o[0], o[1], o[2],  o[3]);
    qo[1] = make_float4(o[4], o[5], o[6],  o[7]);
    qo[2] = make_float4(o[8], o[9], o[10], o[11]);
    ko[0] = make_float4(o[12], o[13], o[14], o[15]);
    ko[1] = make_float4(o[16], o[17], o[18], o[19]);
    ko[2] = make_float4(o[20], o[21], o[22], o[23]);
    vo[0] = make_float4(o[24], o[25], o[26], o[27]);
    vo[1] = make_float4(o[28], o[29], o[30], o[31]);
    vo[2] = make_float4(o[32], o[33], o[34], o[35]);
}

// =====================================================================
// Kernel 2: attention. Block = (batch b, 64 query rows), 256 threads,
// 4 threads per row, each owning 512 keys (interleaved p = 4*it+sub for
// conflict-free LDS). Full per-batch K staged in shared as key-pair
// float2's. Scores via FFMA2 (2 keys at once). Candidate-buffer trick:
// only keys with s > max-30 can contribute (exp underflow), so attn@v
// touches ~7 keys per thread. Rare buffer overflow -> full rescan.
// =====================================================================
#define NCAND 16

__global__ __launch_bounds__(256, 2) void attn_kernel(
    const int* __restrict__ mask,
    float* __restrict__ outp)
{
    extern __shared__ float smem[];
    float* skp   = smem;            // 1024 key-pairs * 12 float2 = 24576 floats (96KB)
    float* sbias = smem + 24576;    // 1024 float2 bias pairs (8KB)

    const int tid  = threadIdx.x;
    const int b    = blockIdx.x >> 5;
    const int tile = blockIdx.x & 31;
    const int sub  = tid & 3;
    const long rowG = (long)b * SS + tile * 64 + (tid >> 2);

    // stage K as pair-interleaved: skp[(t/2)*12 + h] = (k[t][h], k[t+1][h])
    const float* kb = g_k + (long)b * SS * HH;
    for (int i = tid; i < SS * HH; i += 256) {
        int t = i / HH;
        int h = i - t * HH;
        skp[((t >> 1) * HH + h) * 2 + (t & 1)] = kb[i];
    }
    const int* mb = mask + b * SS;
    for (int i = tid; i < SS / 2; i += 256) {
        sbias[2 * i]     = mb[2 * i]     ? 0.f : -1e30f;
        sbias[2 * i + 1] = mb[2 * i + 1] ? 0.f : -1e30f;
    }
    __syncthreads();

    // per-thread q, packed (q_h, q_h)
    const float4* qr4 = (const float4*)(g_q + rowG * HH);
    float4 qa = qr4[0], qb4 = qr4[1], qc = qr4[2];
    float q[12] = {qa.x, qa.y, qa.z, qa.w, qb4.x, qb4.y, qb4.z, qb4.w,
                   qc.x, qc.y, qc.z, qc.w};
    ull q2[12];
#pragma unroll
    for (int h = 0; h < 12; h++) q2[h] = pk2(q[h], q[h]);

    const float scale = 0.28867513459481287f;   // 1/sqrt(12)
    const ull scale2 = pk2(scale, scale);

    float m = __int_as_float(0xff800000);       // -inf
    float cs[NCAND];
    int   ci[NCAND];
    int cn = 0, ovf = 0;

    // ---------- pass 1: scores, running max, candidate collection ----------
    for (int it = 0; it < 256; it++) {
        int p = (it << 2) + sub;                // interleave: conflict-free banks
        const ulonglong2* kp = ((const ulonglong2*)skp) + (size_t)p * 6;
        ull a0 = 0ULL, a1 = 0ULL;
#pragma unroll
        for (int j = 0; j < 6; j++) {
            ulonglong2 u = kp[j];
            fma2(a0, q2[2 * j],     u.x);
            fma2(a1, q2[2 * j + 1], u.y);
        }
        ull d = add2(a0, a1);
        ull s2 = ((const ull*)sbias)[p];
        fma2(s2, d, scale2);                    // s = dot*scale + bias
        float s0, s1;
        upk2(s2, s0, s1);

        if (s0 > m - 30.f) {
            m = fmaxf(m, s0);
            if (cn < NCAND) { cs[cn] = s0; ci[cn] = 2 * p; cn++; } else ovf = 1;
        }
        if (s1 > m - 30.f) {
            m = fmaxf(m, s1);
            if (cn < NCAND) { cs[cn] = s1; ci[cn] = 2 * p + 1; cn++; } else ovf = 1;
        }
    }

    // row max across the 4 sub-threads (adjacent lanes)
#pragma unroll
    for (int off = 1; off < 4; off <<= 1)
        m = fmaxf(m, __shfl_xor_sync(0xffffffffu, m, off));

    // ---------- pass 2: softmax-weighted V over candidates ----------
    const float* vb = g_v + (long)b * SS * HH;
    float den = 0.f;
    float o[12];
#pragma unroll
    for (int h = 0; h < 12; h++) o[h] = 0.f;

    if (!ovf) {
        for (int c = 0; c < cn; c++) {
            float pe = __expf(cs[c] - m);
            if (pe > 0.f) {
                den += pe;
                const float4* vr = (const float4*)(vb + (long)ci[c] * HH);
                float4 v0 = vr[0], v1 = vr[1], v2 = vr[2];
                o[0] += pe * v0.x;  o[1] += pe * v0.y;  o[2] += pe * v0.z;  o[3] += pe * v0.w;
                o[4] += pe * v1.x;  o[5] += pe * v1.y;  o[6] += pe * v1.z;  o[7] += pe * v1.w;
                o[8] += pe * v2.x;  o[9] += pe * v2.y;  o[10]+= pe * v2.z;  o[11]+= pe * v2.w;
            }
        }
    } else {
        // rare fallback: rescan all 512 keys of this thread
        for (int it = 0; it < 256; it++) {
            int p = (it << 2) + sub;
            const ulonglong2* kp = ((const ulonglong2*)skp) + (size_t)p * 6;
            ull a0 = 0ULL, a1 = 0ULL;
#pragma unroll
            for (int j = 0; j < 6; j++) {
                ulonglong2 u = kp[j];
                fma2(a0, q2[2 * j],     u.x);
                fma2(a1, q2[2 * j + 1], u.y);
            }
            ull d = add2(a0, a1);
            ull s2 = ((const ull*)sbias)[p];
            fma2(s2, d, scale2);
            float s0, s1;
            upk2(s2, s0, s1);
#pragma unroll
            for (int half = 0; half < 2; half++) {
                float sv = half ? s1 : s0;
                int   ti = 2 * p + half;
                if (sv - m > -40.f) {
                    float pe = __expf(sv - m);
                    den += pe;
                    const float4* vr = (const float4*)(vb + (long)ti * HH);
                    float4 v0 = vr[0], v1 = vr[1], v2 = vr[2];
                    o[0] += pe * v0.x;  o[1] += pe * v0.y;  o[2] += pe * v0.z;  o[3] += pe * v0.w;
                    o[4] += pe * v1.x;  o[5] += pe * v1.y;  o[6] += pe * v1.z;  o[7] += pe * v1.w;
                    o[8] += pe * v2.x;  o[9] += pe * v2.y;  o[10]+= pe * v2.z;  o[11]+= pe * v2.w;
                }
            }
        }
    }

    // reduce (den, o[12]) across the 4 sub-threads
#pragma unroll
    for (int off = 1; off < 4; off <<= 1) {
        den += __shfl_xor_sync(0xffffffffu, den, off);
#pragma unroll
        for (int h = 0; h < 12; h++)
            o[h] += __shfl_xor_sync(0xffffffffu, o[h], off);
    }

    if (sub == 0) {
        float inv = 1.f / den;
        float* op = outp + rowG * HH;
#pragma unroll
        for (int h = 0; h < 12; h++) op[h] = o[h] * inv;
    }
}

// =====================================================================
// launch
// =====================================================================
extern "C" void kernel_launch(void* const* d_in, const int* in_sizes, int n_in,
                              void* d_out, int out_size) {
    const float* x    = (const float*)d_in[0];
    const int*   mask = (const int*)d_in[1];
    const float* wk   = (const float*)d_in[2];   // key_weight
    const float* wq   = (const float*)d_in[3];   // query_weight
    const float* wv   = (const float*)d_in[4];   // value_weight
    float* out = (float*)d_out;

    const int attn_smem = (24576 + 2048) * 4;    // 106496 B
    cudaFuncSetAttribute(attn_kernel,
                         cudaFuncAttributeMaxDynamicSharedMemorySize, attn_smem);

    proj_kernel<<<BB * SS / 64, 64>>>(x, wq, wk, wv);
    attn_kernel<<<BB * 32, 256, attn_smem>>>(mask, out);
}